// round 10
// baseline (speedup 1.0000x reference)
#include <cuda_runtime.h>
#include <cuda_bf16.h>

// One-hop neighbor sampling with replacement (EdgeSampler), float32 output.
// Geometry: NUM_NODES=1e6, B=256, R=512, S=16 -> 131072 seeds, SEC=2097152.
// Output layout (validated rel_err=0): float32 [src | tgt | valid], SEC each.
//
// R10: block-specialized overlap. Traffic is at its floor (~41MB); the lever
// is achieved DRAM BW (43%). Gather blocks (2048) run the 3-stage latency
// chain and store ONLY tgt; stream blocks (1024, interleaved by bid%3) write
// src+valid with a 2-stage chain, keeping DRAM queues fed while gather
// chains resolve.

#define N_SEEDS   131072
#define N_QUADS   (N_SEEDS * 4)       // 524288
#define SEC       (N_SEEDS * 16)      // 2097152 floats per section
#define HALF_Q    (N_QUADS / 2)       // 262144

__global__ __launch_bounds__(256) void edge_sampler_kernel(
    const int*    __restrict__ seeds,
    const int*    __restrict__ rowp,
    const int*    __restrict__ col,
    const float4* __restrict__ rnd,     // [N_QUADS]
    float4* __restrict__ out_src,       // [N_QUADS]
    float4* __restrict__ out_tgt,       // [N_QUADS]
    float4* __restrict__ out_val,       // [N_QUADS]
    int row_max_idx)
{
    const unsigned bid = blockIdx.x;
    const unsigned r3  = bid % 3u;

    if (r3 < 2u) {
        // ---- GATHER block: tgt section only ----
        const unsigned u = ((bid / 3u) * 2u + r3) * 256u + threadIdx.x;  // < N_QUADS
        const unsigned t = u >> 2;

        const int sid = __ldg(&seeds[t]);
        const int c   = min(max(sid, 0), row_max_idx);

        const int    s = __ldg(&rowp[c]);
        const int    e = __ldg(&rowp[c + 1]);
        const float4 r = __ldg(&rnd[u]);

        const int   d  = e - s;
        const float df = (float)d;
        const int   cl = max(d - 1, 0);
        const bool  vb = (d > 0);

        const int p0 = vb ? s + min((int)(r.x * df), cl) : 0;
        const int p1 = vb ? s + min((int)(r.y * df), cl) : 0;
        const int p2 = vb ? s + min((int)(r.z * df), cl) : 0;
        const int p3 = vb ? s + min((int)(r.w * df), cl) : 0;

        const int g0 = __ldg(&col[p0]);
        const int g1 = __ldg(&col[p1]);
        const int g2 = __ldg(&col[p2]);
        const int g3 = __ldg(&col[p3]);

        out_tgt[u] = make_float4((float)g0, (float)g1, (float)g2, (float)g3);
    } else {
        // ---- STREAM block: src + valid sections, 2 quads per thread ----
        const unsigned v = (bid / 3u) * 256u + threadIdx.x;     // < HALF_Q
        const unsigned q0 = v;
        const unsigned q1 = v + HALF_Q;

        const int t0 = q0 >> 2;
        const int t1 = q1 >> 2;

        const int sid0 = __ldg(&seeds[t0]);
        const int sid1 = __ldg(&seeds[t1]);
        const int c0 = min(max(sid0, 0), row_max_idx);
        const int c1 = min(max(sid1, 0), row_max_idx);

        const int s0 = __ldg(&rowp[c0]);
        const int e0 = __ldg(&rowp[c0 + 1]);
        const int s1 = __ldg(&rowp[c1]);
        const int e1 = __ldg(&rowp[c1 + 1]);

        const float vf0 = (e0 - s0 > 0) ? 1.0f : 0.0f;
        const float vf1 = (e1 - s1 > 0) ? 1.0f : 0.0f;
        const float sf0 = (float)sid0;
        const float sf1 = (float)sid1;

        out_src[q0] = make_float4(sf0, sf0, sf0, sf0);
        out_val[q0] = make_float4(vf0, vf0, vf0, vf0);
        out_src[q1] = make_float4(sf1, sf1, sf1, sf1);
        out_val[q1] = make_float4(vf1, vf1, vf1, vf1);
    }
}

extern "C" void kernel_launch(void* const* d_in, const int* in_sizes, int n_in,
                              void* d_out, int out_size)
{
    // ---- Bind inputs by size ratios (order- and unit-invariant) ----
    int idx_seed = 0;
    for (int i = 1; i < n_in; i++)
        if (in_sizes[i] < in_sizes[idx_seed]) idx_seed = i;

    int idx_col = 0;
    for (int i = 1; i < n_in; i++)
        if (in_sizes[i] > in_sizes[idx_col]) idx_col = i;

    int idx_rand = -1;
    for (int i = 0; i < n_in; i++) {
        if (i != idx_seed && i != idx_col &&
            (long long)in_sizes[i] == 16LL * (long long)in_sizes[idx_seed]) {
            idx_rand = i; break;
        }
    }
    int idx_row = -1;
    for (int i = 0; i < n_in; i++)
        if (i != idx_seed && i != idx_col && i != idx_rand) { idx_row = i; break; }
    if (idx_rand < 0) idx_rand = idx_row;

    const int*    seeds = (const int*)d_in[idx_seed];
    const int*    rowp  = (const int*)d_in[idx_row];
    const int*    col   = (const int*)d_in[idx_col];
    const float4* rnd   = (const float4*)d_in[idx_rand];

    int row_max_idx = in_sizes[idx_row] - 2;
    if (row_max_idx < 0) row_max_idx = 0;

    float* out = (float*)d_out;
    float4* out_src = (float4*)(out);
    float4* out_tgt = (float4*)(out + SEC);
    float4* out_val = (float4*)(out + 2 * SEC);

    // 2048 gather blocks + 1024 stream blocks, interleaved 2:1 by bid%3.
    const int blocks = 3072;
    edge_sampler_kernel<<<blocks, 256>>>(
        seeds, rowp, col, rnd, out_src, out_tgt, out_val, row_max_idx);
}

// round 11
// speedup vs baseline: 1.4985x; 1.4985x over previous
#include <cuda_runtime.h>
#include <cuda_bf16.h>

// One-hop neighbor sampling with replacement (EdgeSampler), float32 output.
// Geometry: NUM_NODES=1e6, B=256, R=512, S=16 -> 131072 seeds, SEC=2097152.
// Output layout (validated rel_err=0 x5): float32 [src | tgt | valid], SEC each.
//
// R11: one-wave + 2 independent chains per thread, 32-bit math only.
//   262144 threads (1024 blocks x 256) -> with ~28 regs this is 8 blocks/SM
//   = 64 warps/SM = ONE full wave. Each thread: 2 independent seed-quads
//   (q, q+HALF) with batched front-loads; src/valid stored BEFORE gathers so
//   write traffic drains while gather chains resolve.

#define N_SEEDS 131072
#define N_QUADS (N_SEEDS * 4)          // 524288
#define HALF_Q  (N_QUADS / 2)          // 262144
#define SEC     (N_SEEDS * 16)         // 2097152 floats per section

__global__ __launch_bounds__(256) void edge_sampler_kernel(
    const int*    __restrict__ seeds,
    const int*    __restrict__ rowp,
    const int*    __restrict__ col,
    const float4* __restrict__ rnd,     // [N_QUADS]
    float4* __restrict__ out_src,       // [N_QUADS]
    float4* __restrict__ out_tgt,       // [N_QUADS]
    float4* __restrict__ out_val,       // [N_QUADS]
    int row_max_idx)
{
    const unsigned v  = blockIdx.x * 256u + threadIdx.x;   // < HALF_Q
    const unsigned q0 = v;
    const unsigned q1 = v + (unsigned)HALF_Q;

    // ---- Stage 1: two independent seed loads (batched) ----
    const int sid0 = __ldg(&seeds[q0 >> 2]);
    const int sid1 = __ldg(&seeds[q1 >> 2]);
    const int c0 = min(max(sid0, 0), row_max_idx);
    const int c1 = min(max(sid1, 0), row_max_idx);

    // ---- Stage 2: row_ptr pairs + uniforms (all independent, batched) ----
    const int    s0 = __ldg(&rowp[c0]);
    const int    e0 = __ldg(&rowp[c0 + 1]);
    const int    s1 = __ldg(&rowp[c1]);
    const int    e1 = __ldg(&rowp[c1 + 1]);
    const float4 r0 = __ldg(&rnd[q0]);
    const float4 r1 = __ldg(&rnd[q1]);

    const int d0 = e0 - s0;
    const int d1 = e1 - s1;
    const bool vb0 = (d0 > 0);
    const bool vb1 = (d1 > 0);

    // ---- Early stores: src + valid don't depend on gathers; drain now ----
    const float sf0 = (float)sid0;
    const float sf1 = (float)sid1;
    const float vf0 = vb0 ? 1.0f : 0.0f;
    const float vf1 = vb1 ? 1.0f : 0.0f;
    out_src[q0] = make_float4(sf0, sf0, sf0, sf0);
    out_val[q0] = make_float4(vf0, vf0, vf0, vf0);
    out_src[q1] = make_float4(sf1, sf1, sf1, sf1);
    out_val[q1] = make_float4(vf1, vf1, vf1, vf1);

    // ---- Gather positions (idx >= 0 by construction; clamp high only) ----
    const float df0 = (float)d0;
    const float df1 = (float)d1;
    const int cl0 = max(d0 - 1, 0);
    const int cl1 = max(d1 - 1, 0);

    const int p00 = vb0 ? s0 + min((int)(r0.x * df0), cl0) : 0;
    const int p01 = vb0 ? s0 + min((int)(r0.y * df0), cl0) : 0;
    const int p02 = vb0 ? s0 + min((int)(r0.z * df0), cl0) : 0;
    const int p03 = vb0 ? s0 + min((int)(r0.w * df0), cl0) : 0;
    const int p10 = vb1 ? s1 + min((int)(r1.x * df1), cl1) : 0;
    const int p11 = vb1 ? s1 + min((int)(r1.y * df1), cl1) : 0;
    const int p12 = vb1 ? s1 + min((int)(r1.z * df1), cl1) : 0;
    const int p13 = vb1 ? s1 + min((int)(r1.w * df1), cl1) : 0;

    // ---- Stage 3: eight independent gathers in flight together ----
    const int g00 = __ldg(&col[p00]);
    const int g01 = __ldg(&col[p01]);
    const int g02 = __ldg(&col[p02]);
    const int g03 = __ldg(&col[p03]);
    const int g10 = __ldg(&col[p10]);
    const int g11 = __ldg(&col[p11]);
    const int g12 = __ldg(&col[p12]);
    const int g13 = __ldg(&col[p13]);

    out_tgt[q0] = make_float4((float)g00, (float)g01, (float)g02, (float)g03);
    out_tgt[q1] = make_float4((float)g10, (float)g11, (float)g12, (float)g13);
}

extern "C" void kernel_launch(void* const* d_in, const int* in_sizes, int n_in,
                              void* d_out, int out_size)
{
    // ---- Bind inputs by size ratios (order- and unit-invariant) ----
    int idx_seed = 0;
    for (int i = 1; i < n_in; i++)
        if (in_sizes[i] < in_sizes[idx_seed]) idx_seed = i;

    int idx_col = 0;
    for (int i = 1; i < n_in; i++)
        if (in_sizes[i] > in_sizes[idx_col]) idx_col = i;

    int idx_rand = -1;
    for (int i = 0; i < n_in; i++) {
        if (i != idx_seed && i != idx_col &&
            (long long)in_sizes[i] == 16LL * (long long)in_sizes[idx_seed]) {
            idx_rand = i; break;
        }
    }
    int idx_row = -1;
    for (int i = 0; i < n_in; i++)
        if (i != idx_seed && i != idx_col && i != idx_rand) { idx_row = i; break; }
    if (idx_rand < 0) idx_rand = idx_row;

    const int*    seeds = (const int*)d_in[idx_seed];
    const int*    rowp  = (const int*)d_in[idx_row];
    const int*    col   = (const int*)d_in[idx_col];
    const float4* rnd   = (const float4*)d_in[idx_rand];

    int row_max_idx = in_sizes[idx_row] - 2;
    if (row_max_idx < 0) row_max_idx = 0;

    float* out = (float*)d_out;
    float4* out_src = (float4*)(out);
    float4* out_tgt = (float4*)(out + SEC);
    float4* out_val = (float4*)(out + 2 * SEC);

    const int threads = 256;
    const int blocks  = HALF_Q / threads;   // 1024
    edge_sampler_kernel<<<blocks, threads>>>(
        seeds, rowp, col, rnd, out_src, out_tgt, out_val, row_max_idx);
}